// round 1
// baseline (speedup 1.0000x reference)
#include <cuda_runtime.h>
#include <math.h>

// ---------------- problem constants ----------------
#define PB   4
#define PN1  2048
#define PN2  512
#define PD   768
#define PH   8
#define PDK  64
#define PDV  96
#define PNRP 96
#define PDY0 1536
#define PDFF 1536
#define PMQ  2560              // needed pos rows: m = i - j + 511 in [0, 2558]
#define PSCALE 0.125f          // DK^-0.5

// ---------------- scratch layout (floats) ----------------
#define OFF_Y      0L
#define OFF_X1     (OFF_Y    + (long)PB*PN2*PD)        // 1,572,864
#define OFF_Y1     (OFF_X1   + (long)PB*PN1*PD)        // +6,291,456
#define OFF_Q      (OFF_Y1   + (long)PB*PN2*PD)
#define OFF_K      (OFF_Q    + (long)PB*PN1*PH*PDK)
#define OFF_KB     (OFF_K    + (long)PB*PN2*PH*PDK)
#define OFF_V1     (OFF_KB   + (long)PB*PN2*PH*PDK)
#define OFF_V2     (OFF_V1   + (long)PB*PN1*PH*PDV)
#define OFF_POS    (OFF_V2   + (long)PB*PN2*PH*PDV)
#define OFF_RELQ   (OFF_POS  + (long)PMQ*PNRP)
#define OFF_REL    (OFF_RELQ + (long)PMQ*PH*PDK)
#define OFF_ATT    (OFF_REL  + (long)PB*PH*PN2*PMQ)
#define OFF_OUT1   (OFF_ATT  + (long)PB*PH*PN1*PN2)
#define OFF_OUT2   (OFF_OUT1 + (long)PB*PN1*PH*PDV)
#define OFF_X4     (OFF_OUT2 + (long)PB*PN2*PH*PDV)
#define OFF_Y4     (OFF_X4   + (long)PB*PN1*PD)
#define OFF_HID    (OFF_Y4   + (long)PB*PN2*PD)
#define SCRATCH_TOTAL (OFF_HID + (long)PB*PN1*PDFF)

__device__ float g_scratch[SCRATCH_TOTAL];

// ---------------- generic tiled GEMM ----------------
// C[m,n] = alpha * sum_k Aop[m,k] * Bop[k,n]  (+bias[n]) (+Res[m,n]) (relu)
// Aop = A[m*lda+k] (TA=0) or A[k*lda+m] (TA=1)
// Bop = B[k*ldb+n] (TB=0) or B[n*ldb+k] (TB=1)
// Batch z: b = z/Hn, h = z%Hn; pointers offset by b*s?b + h*s?h.
#define BM 64
#define BN 64
#define BK 16

template <bool TA, bool TB>
__global__ __launch_bounds__(256) void gemm_k(
    const float* __restrict__ A, const float* __restrict__ B,
    const float* __restrict__ bias, const float* __restrict__ Res,
    float* __restrict__ C,
    int M, int N, int K, int lda, int ldb, int ldc,
    long sAb, long sAh, long sBb, long sBh, long sCb, long sCh, int Hn,
    float alpha, int doRelu)
{
    int z = blockIdx.z;
    int bb = z / Hn, hh = z % Hn;
    A += bb * sAb + hh * sAh;
    B += bb * sBb + hh * sBh;
    C += bb * sCb + hh * sCh;
    if (Res) Res += bb * sCb + hh * sCh;

    __shared__ float As[BK][BM];
    __shared__ float Bs[BK][BN];

    int m0 = blockIdx.y * BM;
    int n0 = blockIdx.x * BN;
    int tx = threadIdx.x, ty = threadIdx.y;
    int tid = ty * 16 + tx;

    float acc[4][4] = {};

    for (int k0 = 0; k0 < K; k0 += BK) {
        if (!TA) {
            for (int idx = tid; idx < BM * BK; idx += 256) {
                int m = idx / BK, kk = idx % BK;
                float v = 0.f;
                if (m0 + m < M) v = A[(long)(m0 + m) * lda + (k0 + kk)];
                As[kk][m] = v;
            }
        } else {
            for (int idx = tid; idx < BM * BK; idx += 256) {
                int kk = idx / BM, m = idx % BM;
                float v = 0.f;
                if (m0 + m < M) v = A[(long)(k0 + kk) * lda + (m0 + m)];
                As[kk][m] = v;
            }
        }
        if (!TB) {
            for (int idx = tid; idx < BN * BK; idx += 256) {
                int kk = idx / BN, n = idx % BN;
                float v = 0.f;
                if (n0 + n < N) v = B[(long)(k0 + kk) * ldb + (n0 + n)];
                Bs[kk][n] = v;
            }
        } else {
            for (int idx = tid; idx < BN * BK; idx += 256) {
                int n = idx / BK, kk = idx % BK;
                float v = 0.f;
                if (n0 + n < N) v = B[(long)(n0 + n) * ldb + (k0 + kk)];
                Bs[kk][n] = v;
            }
        }
        __syncthreads();
        #pragma unroll
        for (int kk = 0; kk < BK; kk++) {
            float a[4], bq[4];
            #pragma unroll
            for (int i = 0; i < 4; i++) a[i] = As[kk][ty * 4 + i];
            #pragma unroll
            for (int j = 0; j < 4; j++) bq[j] = Bs[kk][tx * 4 + j];
            #pragma unroll
            for (int i = 0; i < 4; i++)
                #pragma unroll
                for (int j = 0; j < 4; j++)
                    acc[i][j] += a[i] * bq[j];
        }
        __syncthreads();
    }

    #pragma unroll
    for (int i = 0; i < 4; i++) {
        int m = m0 + ty * 4 + i;
        if (m >= M) continue;
        #pragma unroll
        for (int j = 0; j < 4; j++) {
            int n = n0 + tx * 4 + j;
            if (n >= N) continue;
            float v = acc[i][j] * alpha;
            if (bias) v += bias[n];
            if (Res)  v += Res[(long)m * ldc + n];
            if (doRelu) v = fmaxf(v, 0.f);
            C[(long)m * ldc + n] = v;
        }
    }
}

// ---------------- LayerNorm: one block per row of width 768 ----------------
__device__ __forceinline__ float warpSum(float v) {
    #pragma unroll
    for (int o = 16; o; o >>= 1) v += __shfl_xor_sync(0xffffffffu, v, o);
    return v;
}
__device__ __forceinline__ float warpMax(float v) {
    #pragma unroll
    for (int o = 16; o; o >>= 1) v = fmaxf(v, __shfl_xor_sync(0xffffffffu, v, o));
    return v;
}

__global__ __launch_bounds__(256) void ln_k(const float* __restrict__ X,
                                            const float* __restrict__ g,
                                            const float* __restrict__ bta,
                                            float* __restrict__ Y)
{
    long row = blockIdx.x;
    const float* xr = X + row * PD;
    float* yr = Y + row * PD;
    int t = threadIdx.x, lane = t & 31, wid = t >> 5;

    float s1 = 0.f, s2 = 0.f;
    for (int c = t; c < PD; c += 256) { float v = xr[c]; s1 += v; s2 += v * v; }
    s1 = warpSum(s1); s2 = warpSum(s2);
    __shared__ float sA[8], sB[8];
    if (lane == 0) { sA[wid] = s1; sB[wid] = s2; }
    __syncthreads();
    float t1 = 0.f, t2 = 0.f;
    #pragma unroll
    for (int w = 0; w < 8; w++) { t1 += sA[w]; t2 += sB[w]; }
    float mean = t1 / (float)PD;
    float var  = t2 / (float)PD - mean * mean;
    float rs = rsqrtf(var + 1e-5f);
    for (int c = t; c < PD; c += 256)
        yr[c] = (xr[c] - mean) * rs * g[c] + bta[c];
}

// ---------------- Enformer positional features, rows m < PMQ ----------------
__global__ void pos_k(float* __restrict__ pos)
{
    int m = blockIdx.x * blockDim.x + threadIdx.x;
    if (m >= PMQ) return;
    float d = (float)(m - (PN1 - 1));
    float ad = fabsf(d);

    float fe[16], fc[16], fg[16];
    float pmax = 0.f;
    const float ln2 = 0.6931471805599453f;
    #pragma unroll
    for (int i = 0; i < 16; i++) {
        // exponential half-life basis: half_life = 2^linspace(3, 11, 16)
        float e = 3.0f + 8.0f * (float)i / 15.0f;
        float hl = exp2f(e);
        fe[i] = expf(-ln2 / hl * ad);
        // central mask: cw = 2^(i+1) - 1
        float cw = exp2f((float)(i + 1)) - 1.0f;
        fc[i] = (cw > ad) ? 1.0f : 0.0f;
        // gamma pdf: mean = linspace(128, 2048, 16) = 128*(i+1); stddev = 64
        float mean = 128.0f * (float)(i + 1);
        float conc = (mean / 64.0f) * (mean / 64.0f);
        float rate = mean / 4096.0f;
        float logp = (conc - 1.0f) * logf(ad) - rate * ad
                   - (lgammaf(conc) - conc * logf(rate));
        float prob = expf(logp) + 1e-8f;
        fg[i] = prob;
        pmax = fmaxf(pmax, prob);
    }
    float sgn = (d > 0.f) ? 1.f : ((d < 0.f) ? -1.f : 0.f);
    float inv = 1.0f / pmax;
    float* row = pos + (long)m * PNRP;
    #pragma unroll
    for (int i = 0; i < 16; i++) {
        float gv = fg[i] * inv;
        row[i]      = fe[i];
        row[16 + i] = fc[i];
        row[32 + i] = gv;
        row[48 + i] = sgn * fe[i];
        row[64 + i] = sgn * fc[i];
        row[80 + i] = sgn * gv;
    }
}

// ---------------- kb = k * SCALE + rel_pos_bias ----------------
__global__ void kb_k(const float* __restrict__ k, const float* __restrict__ rpb,
                     float* __restrict__ kb, int total)
{
    for (int i = blockIdx.x * blockDim.x + threadIdx.x; i < total;
         i += gridDim.x * blockDim.x)
        kb[i] = k[i] * PSCALE + rpb[i & 511];   // 511 = H*DK - 1
}

// ---------------- fused rel-shift gather + softmax over N2 ----------------
// att holds content logits [z, i, j]; rel is [z, j, m], m = i - j + 511.
__global__ __launch_bounds__(128) void softmax_k(float* __restrict__ att,
                                                 const float* __restrict__ rel)
{
    int i = blockIdx.x;            // n1 index
    long z = blockIdx.y;           // b*H + h
    float* row = att + (z * PN1 + i) * (long)PN2;
    const float* relz = rel + z * (long)PN2 * PMQ;
    int t = threadIdx.x, lane = t & 31, wid = t >> 5;

    float v[4];
    float mx = -1e30f;
    #pragma unroll
    for (int u = 0; u < 4; u++) {
        int j = t + u * 128;
        float val = row[j] + relz[(long)j * PMQ + (i + (PN2 - 1) - j)];
        v[u] = val;
        mx = fmaxf(mx, val);
    }
    __shared__ float sh[4];
    mx = warpMax(mx);
    if (lane == 0) sh[wid] = mx;
    __syncthreads();
    float gmx = fmaxf(fmaxf(sh[0], sh[1]), fmaxf(sh[2], sh[3]));
    __syncthreads();

    float s = 0.f;
    #pragma unroll
    for (int u = 0; u < 4; u++) { v[u] = expf(v[u] - gmx); s += v[u]; }
    s = warpSum(s);
    if (lane == 0) sh[wid] = s;
    __syncthreads();
    float gs = sh[0] + sh[1] + sh[2] + sh[3];
    float inv = 1.0f / gs;
    #pragma unroll
    for (int u = 0; u < 4; u++) row[t + u * 128] = v[u] * inv;
}

// ---------------- host orchestration ----------------
static inline dim3 ggrid(int M, int N, int Z) {
    return dim3((unsigned)((N + BN - 1) / BN), (unsigned)((M + BM - 1) / BM), (unsigned)Z);
}

extern "C" void kernel_launch(void* const* d_in, const int* in_sizes, int n_in,
                              void* d_out, int out_size)
{
    const float* x     = (const float*)d_in[0];
    const float* y0    = (const float*)d_in[1];
    const float* W_res = (const float*)d_in[2];
    const float* lnx_g = (const float*)d_in[3];
    const float* lnx_b = (const float*)d_in[4];
    const float* lny_g = (const float*)d_in[5];
    const float* lny_b = (const float*)d_in[6];
    const float* Wq    = (const float*)d_in[7];
    const float* Wk    = (const float*)d_in[8];
    const float* Wv1   = (const float*)d_in[9];
    const float* Wv2   = (const float*)d_in[10];
    const float* Wo1   = (const float*)d_in[11];
    const float* bo1   = (const float*)d_in[12];
    const float* Wo2   = (const float*)d_in[13];
    const float* bo2   = (const float*)d_in[14];
    const float* Wrel  = (const float*)d_in[15];
    const float* rpb   = (const float*)d_in[16];
    const float* fx_g  = (const float*)d_in[17];
    const float* fx_b  = (const float*)d_in[18];
    const float* fx_w1 = (const float*)d_in[19];
    const float* fx_b1 = (const float*)d_in[20];
    const float* fx_w2 = (const float*)d_in[21];
    const float* fx_b2 = (const float*)d_in[22];
    const float* fy_g  = (const float*)d_in[23];
    const float* fy_b  = (const float*)d_in[24];
    const float* fy_w1 = (const float*)d_in[25];
    const float* fy_b1 = (const float*)d_in[26];
    const float* fy_w2 = (const float*)d_in[27];
    const float* fy_b2 = (const float*)d_in[28];

    float* S = nullptr;
    cudaGetSymbolAddress((void**)&S, g_scratch);
    float* gy   = S + OFF_Y;
    float* gx1  = S + OFF_X1;
    float* gy1  = S + OFF_Y1;
    float* gq   = S + OFF_Q;
    float* gk   = S + OFF_K;
    float* gkb  = S + OFF_KB;
    float* gv1  = S + OFF_V1;
    float* gv2  = S + OFF_V2;
    float* gpos = S + OFF_POS;
    float* grq  = S + OFF_RELQ;
    float* grel = S + OFF_REL;
    float* gatt = S + OFF_ATT;
    float* go1  = S + OFF_OUT1;
    float* go2  = S + OFF_OUT2;
    float* gx4  = S + OFF_X4;
    float* gy4  = S + OFF_Y4;
    float* gh   = S + OFF_HID;

    float* outx = (float*)d_out;
    float* outy = outx + (long)PB * PN1 * PD;

    dim3 tb(16, 16);
    const int HDK = PH * PDK;   // 512
    const int HDV = PH * PDV;   // 768

    // x1 = LN(x), y = y0 @ W_res, y1 = LN(y)
    ln_k<<<PB * PN1, 256>>>(x, lnx_g, lnx_b, gx1);
    gemm_k<false,false><<<ggrid(PB*PN2, PD, 1), tb>>>(y0, W_res, nullptr, nullptr, gy,
        PB*PN2, PD, PDY0, PDY0, PD, PD, 0,0,0,0,0,0, 1, 1.f, 0);
    ln_k<<<PB * PN2, 256>>>(gy, lny_g, lny_b, gy1);

    // q, k, v2, v1 projections
    gemm_k<false,false><<<ggrid(PB*PN1, HDK, 1), tb>>>(gx1, Wq, nullptr, nullptr, gq,
        PB*PN1, HDK, PD, PD, HDK, HDK, 0,0,0,0,0,0, 1, 1.f, 0);
    gemm_k<false,false><<<ggrid(PB*PN2, HDK, 1), tb>>>(gy1, Wk, nullptr, nullptr, gk,
        PB*PN2, HDK, PD, PD, HDK, HDK, 0,0,0,0,0,0, 1, 1.f, 0);
    gemm_k<false,false><<<ggrid(PB*PN2, HDV, 1), tb>>>(gy1, Wv2, nullptr, nullptr, gv2,
        PB*PN2, HDV, PD, PD, HDV, HDV, 0,0,0,0,0,0, 1, 1.f, 0);
    gemm_k<false,false><<<ggrid(PB*PN1, HDV, 1), tb>>>(gx1, Wv1, nullptr, nullptr, gv1,
        PB*PN1, HDV, PD, PD, HDV, HDV, 0,0,0,0,0,0, 1, 1.f, 0);

    // positional features + rel_q = pos @ Wrel (only m < PMQ needed)
    pos_k<<<(PMQ + 127) / 128, 128>>>(gpos);
    gemm_k<false,false><<<ggrid(PMQ, HDK, 1), tb>>>(gpos, Wrel, nullptr, nullptr, grq,
        PMQ, HDK, PNRP, PNRP, HDK, HDK, 0,0,0,0,0,0, 1, 1.f, 0);

    // kb = k * SCALE + rel_pos_bias
    kb_k<<<2048, 256>>>(gk, rpb, gkb, PB*PN2*HDK);

    // content logits = SCALE * q @ k^T   (batched over b,h; NT)
    gemm_k<false,true><<<ggrid(PN1, PN2, PB*PH), tb>>>(gq, gk, nullptr, nullptr, gatt,
        PN1, PN2, PDK, HDK, HDK, PN2,
        (long)PN1*HDK, PDK, (long)PN2*HDK, PDK,
        (long)PH*PN1*PN2, (long)PN1*PN2, PH, PSCALE, 0);

    // rel = kb @ rel_q^T  (batched; rel_q shared across b -> sBb = 0)
    gemm_k<false,true><<<ggrid(PN2, PMQ, PB*PH), tb>>>(gkb, grq, nullptr, nullptr, grel,
        PN2, PMQ, PDK, HDK, HDK, PMQ,
        (long)PN2*HDK, PDK, 0L, PDK,
        (long)PH*PN2*PMQ, (long)PN2*PMQ, PH, 1.f, 0);

    // fused rel-shift gather + softmax (in place over gatt)
    softmax_k<<<dim3(PN1, PB*PH), 128>>>(gatt, grel);

    // out1 = attn @ v2   (batched NN)
    gemm_k<false,false><<<ggrid(PN1, PDV, PB*PH), tb>>>(gatt, gv2, nullptr, nullptr, go1,
        PN1, PDV, PN2, PN2, HDV, HDV,
        (long)PH*PN1*PN2, (long)PN1*PN2, (long)PN2*HDV, PDV,
        (long)PN1*HDV, PDV, PH, 1.f, 0);

    // out2 = attn^T @ v1 (batched TN)
    gemm_k<true,false><<<ggrid(PN2, PDV, PB*PH), tb>>>(gatt, gv1, nullptr, nullptr, go2,
        PN2, PDV, PN1, PN2, HDV, HDV,
        (long)PH*PN1*PN2, (long)PN1*PN2, (long)PN1*HDV, PDV,
        (long)PN2*HDV, PDV, PH, 1.f, 0);

    // x4 = x + out1 @ Wo1 + bo1 ;  y4 = y + out2 @ Wo2 + bo2
    gemm_k<false,false><<<ggrid(PB*PN1, PD, 1), tb>>>(go1, Wo1, bo1, x, gx4,
        PB*PN1, PD, HDV, HDV, PD, PD, 0,0,0,0,0,0, 1, 1.f, 0);
    gemm_k<false,false><<<ggrid(PB*PN2, PD, 1), tb>>>(go2, Wo2, bo2, gy, gy4,
        PB*PN2, PD, HDV, HDV, PD, PD, 0,0,0,0,0,0, 1, 1.f, 0);

    // FFN x: x5 = x4 + relu(LN(x4) @ w1 + b1) @ w2 + b2  -> outx
    ln_k<<<PB * PN1, 256>>>(gx4, fx_g, fx_b, gx1);
    gemm_k<false,false><<<ggrid(PB*PN1, PDFF, 1), tb>>>(gx1, fx_w1, fx_b1, nullptr, gh,
        PB*PN1, PDFF, PD, PD, PDFF, PDFF, 0,0,0,0,0,0, 1, 1.f, 1);
    gemm_k<false,false><<<ggrid(PB*PN1, PD, 1), tb>>>(gh, fx_w2, fx_b2, gx4, outx,
        PB*PN1, PD, PDFF, PDFF, PD, PD, 0,0,0,0,0,0, 1, 1.f, 0);

    // FFN y -> outy
    ln_k<<<PB * PN2, 256>>>(gy4, fy_g, fy_b, gy1);
    gemm_k<false,false><<<ggrid(PB*PN2, PDFF, 1), tb>>>(gy1, fy_w1, fy_b1, nullptr, gh,
        PB*PN2, PDFF, PD, PD, PDFF, PDFF, 0,0,0,0,0,0, 1, 1.f, 1);
    gemm_k<false,false><<<ggrid(PB*PN2, PD, 1), tb>>>(gh, fy_w2, fy_b2, gy4, outy,
        PB*PN2, PD, PDFF, PDFF, PD, PD, 0,0,0,0,0,0, 1, 1.f, 0);

    (void)in_sizes; (void)n_in; (void)out_size;
}

// round 3
// speedup vs baseline: 2.9518x; 2.9518x over previous
#include <cuda_runtime.h>
#include <cuda_bf16.h>
#include <cstdint>
#include <math.h>

// ---------------- problem constants ----------------
#define PB   4
#define PN1  2048
#define PN2  512
#define PD   768
#define PH   8
#define PDK  64
#define PDV  96
#define PNRP 96
#define PDY0 1536
#define PDFF 1536
#define PMQ  2560              // needed pos rows: m = i - j + 511 in [0, 2558]
#define PSCALE 0.125f          // DK^-0.5

// ---------------- scratch layout (floats) ----------------
#define OFF_Y      0L
#define OFF_X1     (OFF_Y    + (long)PB*PN2*PD)
#define OFF_Y1     (OFF_X1   + (long)PB*PN1*PD)
#define OFF_Q      (OFF_Y1   + (long)PB*PN2*PD)
#define OFF_K      (OFF_Q    + (long)PB*PN1*PH*PDK)
#define OFF_KB     (OFF_K    + (long)PB*PN2*PH*PDK)
#define OFF_V1     (OFF_KB   + (long)PB*PN2*PH*PDK)
#define OFF_V2     (OFF_V1   + (long)PB*PN1*PH*PDV)
#define OFF_POS    (OFF_V2   + (long)PB*PN2*PH*PDV)
#define OFF_RELQ   (OFF_POS  + (long)PMQ*PNRP)
#define OFF_REL    (OFF_RELQ + (long)PMQ*PH*PDK)
#define OFF_ATT    (OFF_REL  + (long)PB*PH*PN2*PMQ)
#define OFF_OUT1   (OFF_ATT  + (long)PB*PH*PN1*PN2)
#define OFF_OUT2   (OFF_OUT1 + (long)PB*PN1*PH*PDV)
#define OFF_X4     (OFF_OUT2 + (long)PB*PN2*PH*PDV)
#define OFF_Y4     (OFF_X4   + (long)PB*PN1*PD)
#define OFF_HID    (OFF_Y4   + (long)PB*PN2*PD)
#define SCRATCH_TOTAL (OFF_HID + (long)PB*PN1*PDFF)

__device__ float g_scratch[SCRATCH_TOTAL];

// ---------------- bf16x3 tensor-core GEMM ----------------
// C[m,n] = alpha * sum_k Aop[m,k]*Bop[k,n] (+bias[n]) (+Res[m,n]) (relu)
// Requires K % 32 == 0 (true for every call in this graph).
#define BM 128
#define BN 64
#define BK 32
#define SA 40   // padded smem k-stride (conflict-free for ldmatrix)

__device__ __forceinline__ uint32_t sptr(const void* p) {
    return (uint32_t)__cvta_generic_to_shared(p);
}

__device__ __forceinline__ void bsplit(float x, __nv_bfloat16& h, __nv_bfloat16& l) {
    h = __float2bfloat16(x);
    l = __float2bfloat16(x - __bfloat162float(h));
}

__device__ __forceinline__ void ldsm4(uint32_t r[4], const __nv_bfloat16* p) {
    uint32_t a = sptr(p);
    asm volatile("ldmatrix.sync.aligned.m8n8.x4.shared.b16 {%0,%1,%2,%3}, [%4];"
                 : "=r"(r[0]), "=r"(r[1]), "=r"(r[2]), "=r"(r[3]) : "r"(a));
}
__device__ __forceinline__ void ldsm2(uint32_t r[2], const __nv_bfloat16* p) {
    uint32_t a = sptr(p);
    asm volatile("ldmatrix.sync.aligned.m8n8.x2.shared.b16 {%0,%1}, [%2];"
                 : "=r"(r[0]), "=r"(r[1]) : "r"(a));
}
__device__ __forceinline__ void mma16816(float c[4], const uint32_t a[4], const uint32_t b[2]) {
    asm volatile(
        "mma.sync.aligned.m16n8k16.row.col.f32.bf16.bf16.f32 "
        "{%0,%1,%2,%3}, {%4,%5,%6,%7}, {%8,%9}, {%0,%1,%2,%3};"
        : "+f"(c[0]), "+f"(c[1]), "+f"(c[2]), "+f"(c[3])
        : "r"(a[0]), "r"(a[1]), "r"(a[2]), "r"(a[3]), "r"(b[0]), "r"(b[1]));
}

template <bool TA, bool TB>
__global__ __launch_bounds__(256) void gemm_k(
    const float* __restrict__ A, const float* __restrict__ B,
    const float* __restrict__ bias, const float* __restrict__ Res,
    float* __restrict__ C,
    int M, int N, int K, int lda, int ldb, int ldc,
    long sAb, long sAh, long sBb, long sBh, long sCb, long sCh, int Hn,
    float alpha, int doRelu)
{
    int z = blockIdx.z;
    int bb = z / Hn, hh = z % Hn;
    A += bb * sAb + hh * sAh;
    B += bb * sBb + hh * sBh;
    C += bb * sCb + hh * sCh;
    if (Res) Res += bb * sCb + hh * sCh;

    __shared__ __nv_bfloat16 Ash[BM * SA];
    __shared__ __nv_bfloat16 Asl[BM * SA];
    __shared__ __nv_bfloat16 Bsh[BN * SA];
    __shared__ __nv_bfloat16 Bsl[BN * SA];

    int m0 = blockIdx.y * BM;
    int n0 = blockIdx.x * BN;
    int tid = threadIdx.x;
    int w = tid >> 5, lane = tid & 31;
    int wm = (w & 3) * 32;    // warp m-offset within block
    int wn = (w >> 2) * 32;   // warp n-offset within block

    float acc[2][4][4];
    #pragma unroll
    for (int f = 0; f < 2; f++)
        #pragma unroll
        for (int g = 0; g < 4; g++)
            #pragma unroll
            for (int e = 0; e < 4; e++) acc[f][g][e] = 0.f;

    for (int k0 = 0; k0 < K; k0 += BK) {
        // ---- load + split A tile: As[m][k], m<128, k<32 ----
        if (!TA) {
            #pragma unroll
            for (int idx = tid; idx < BM * 8; idx += 256) {
                int m = idx >> 3, kq = (idx & 7) << 2;
                float4 v = make_float4(0.f, 0.f, 0.f, 0.f);
                if (m0 + m < M)
                    v = *(const float4*)(A + (long)(m0 + m) * lda + k0 + kq);
                __nv_bfloat16 h, l;
                bsplit(v.x, h, l); Ash[m*SA + kq + 0] = h; Asl[m*SA + kq + 0] = l;
                bsplit(v.y, h, l); Ash[m*SA + kq + 1] = h; Asl[m*SA + kq + 1] = l;
                bsplit(v.z, h, l); Ash[m*SA + kq + 2] = h; Asl[m*SA + kq + 2] = l;
                bsplit(v.w, h, l); Ash[m*SA + kq + 3] = h; Asl[m*SA + kq + 3] = l;
            }
        } else {
            #pragma unroll
            for (int idx = tid; idx < BK * 32; idx += 256) {
                int k = idx >> 5, mq = (idx & 31) << 2;
                float4 v = make_float4(0.f, 0.f, 0.f, 0.f);
                if (m0 + mq < M)
                    v = *(const float4*)(A + (long)(k0 + k) * lda + m0 + mq);
                __nv_bfloat16 h, l;
                bsplit(v.x, h, l); Ash[(mq+0)*SA + k] = h; Asl[(mq+0)*SA + k] = l;
                bsplit(v.y, h, l); Ash[(mq+1)*SA + k] = h; Asl[(mq+1)*SA + k] = l;
                bsplit(v.z, h, l); Ash[(mq+2)*SA + k] = h; Asl[(mq+2)*SA + k] = l;
                bsplit(v.w, h, l); Ash[(mq+3)*SA + k] = h; Asl[(mq+3)*SA + k] = l;
            }
        }
        // ---- load + split B tile: Bs[n][k], n<64, k<32 ----
        if (TB) {
            #pragma unroll
            for (int idx = tid; idx < BN * 8; idx += 256) {
                int n = idx >> 3, kq = (idx & 7) << 2;
                float4 v = make_float4(0.f, 0.f, 0.f, 0.f);
                if (n0 + n < N)
                    v = *(const float4*)(B + (long)(n0 + n) * ldb + k0 + kq);
                __nv_bfloat16 h, l;
                bsplit(v.x, h, l); Bsh[n*SA + kq + 0] = h; Bsl[n*SA + kq + 0] = l;
                bsplit(v.y, h, l); Bsh[n*SA + kq + 1] = h; Bsl[n*SA + kq + 1] = l;
                bsplit(v.z, h, l); Bsh[n*SA + kq + 2] = h; Bsl[n*SA + kq + 2] = l;
                bsplit(v.w, h, l); Bsh[n*SA + kq + 3] = h; Bsl[n*SA + kq + 3] = l;
            }
        } else {
            #pragma unroll
            for (int idx = tid; idx < BK * 16; idx += 256) {
                int k = idx >> 4, nq = (idx & 15) << 2;
                float4 v = make_float4(0.f, 0.f, 0.f, 0.f);
                int nb = n0 + nq;
                if (nb + 3 < N) {
                    v = *(const float4*)(B + (long)(k0 + k) * ldb + nb);
                } else {
                    const float* bp = B + (long)(k0 + k) * ldb + nb;
                    if (nb + 0 < N) v.x = bp[0];
                    if (nb + 1 < N) v.y = bp[1];
                    if (nb + 2 < N) v.z = bp[2];
                    if (nb + 3 < N) v.w = bp[3];
                }
                __nv_bfloat16 h, l;
                bsplit(v.x, h, l); Bsh[(nq+0)*SA + k] = h; Bsl[(nq+0)*SA + k] = l;
                bsplit(v.y, h, l); Bsh[(nq+1)*SA + k] = h; Bsl[(nq+1)*SA + k] = l;
                bsplit(v.z, h, l); Bsh[(nq+2)*SA + k] = h; Bsl[(nq+2)*SA + k] = l;
                bsplit(v.w, h, l); Bsh[(nq+3)*SA + k] = h; Bsl[(nq+3)*SA + k] = l;
            }
        }
        __syncthreads();

        // ---- tensor-core compute ----
        #pragma unroll
        for (int kk = 0; kk < BK; kk += 16) {
            uint32_t ah[2][4], al[2][4];
            #pragma unroll
            for (int f = 0; f < 2; f++) {
                int row = wm + f * 16 + (lane & 15);
                int col = kk + ((lane >> 4) << 3);
                ldsm4(ah[f], &Ash[row * SA + col]);
                ldsm4(al[f], &Asl[row * SA + col]);
            }
            uint32_t bh[4][2], bl[4][2];
            #pragma unroll
            for (int g = 0; g < 4; g++) {
                int row = wn + g * 8 + (lane & 7);
                int col = kk + (((lane >> 3) & 1) << 3);
                ldsm2(bh[g], &Bsh[row * SA + col]);
                ldsm2(bl[g], &Bsl[row * SA + col]);
            }
            #pragma unroll
            for (int f = 0; f < 2; f++)
                #pragma unroll
                for (int g = 0; g < 4; g++) {
                    mma16816(acc[f][g], ah[f], bh[g]);
                    mma16816(acc[f][g], al[f], bh[g]);
                    mma16816(acc[f][g], ah[f], bl[g]);
                }
        }
        __syncthreads();
    }

    // ---- epilogue ----
    int gid = lane >> 2, tg = lane & 3;
    #pragma unroll
    for (int f = 0; f < 2; f++) {
        #pragma unroll
        for (int g = 0; g < 4; g++) {
            int r0 = m0 + wm + f * 16 + gid;
            int c0 = n0 + wn + g * 8 + tg * 2;
            #pragma unroll
            for (int e = 0; e < 4; e++) {
                int r = r0 + ((e >> 1) << 3);
                int c = c0 + (e & 1);
                if (r >= M || c >= N) continue;
                float v = acc[f][g][e] * alpha;
                if (bias) v += bias[c];
                if (Res)  v += Res[(long)r * ldc + c];
                if (doRelu) v = fmaxf(v, 0.f);
                C[(long)r * ldc + c] = v;
            }
        }
    }
}

// ---------------- LayerNorm ----------------
__device__ __forceinline__ float warpSum(float v) {
    #pragma unroll
    for (int o = 16; o; o >>= 1) v += __shfl_xor_sync(0xffffffffu, v, o);
    return v;
}
__device__ __forceinline__ float warpMax(float v) {
    #pragma unroll
    for (int o = 16; o; o >>= 1) v = fmaxf(v, __shfl_xor_sync(0xffffffffu, v, o));
    return v;
}

__global__ __launch_bounds__(256) void ln_k(const float* __restrict__ X,
                                            const float* __restrict__ g,
                                            const float* __restrict__ bta,
                                            float* __restrict__ Y)
{
    long row = blockIdx.x;
    const float* xr = X + row * PD;
    float* yr = Y + row * PD;
    int t = threadIdx.x, lane = t & 31, wid = t >> 5;

    float s1 = 0.f, s2 = 0.f;
    for (int c = t; c < PD; c += 256) { float v = xr[c]; s1 += v; s2 += v * v; }
    s1 = warpSum(s1); s2 = warpSum(s2);
    __shared__ float sA[8], sB[8];
    if (lane == 0) { sA[wid] = s1; sB[wid] = s2; }
    __syncthreads();
    float t1 = 0.f, t2 = 0.f;
    #pragma unroll
    for (int wI = 0; wI < 8; wI++) { t1 += sA[wI]; t2 += sB[wI]; }
    float mean = t1 / (float)PD;
    float var  = t2 / (float)PD - mean * mean;
    float rs = rsqrtf(var + 1e-5f);
    for (int c = t; c < PD; c += 256)
        yr[c] = (xr[c] - mean) * rs * g[c] + bta[c];
}

// ---------------- Enformer positional features ----------------
__global__ void pos_k(float* __restrict__ pos)
{
    int m = blockIdx.x * blockDim.x + threadIdx.x;
    if (m >= PMQ) return;
    float d = (float)(m - (PN1 - 1));
    float ad = fabsf(d);

    float fe[16], fc[16], fg[16];
    float pmax = 0.f;
    const float ln2 = 0.6931471805599453f;
    #pragma unroll
    for (int i = 0; i < 16; i++) {
        float e = 3.0f + 8.0f * (float)i / 15.0f;
        float hl = exp2f(e);
        fe[i] = expf(-ln2 / hl * ad);
        float cw = exp2f((float)(i + 1)) - 1.0f;
        fc[i] = (cw > ad) ? 1.0f : 0.0f;
        float mean = 128.0f * (float)(i + 1);
        float conc = (mean / 64.0f) * (mean / 64.0f);
        float rate = mean / 4096.0f;
        float logp = (conc - 1.0f) * logf(ad) - rate * ad
                   - (lgammaf(conc) - conc * logf(rate));
        float prob = expf(logp) + 1e-8f;
        fg[i] = prob;
        pmax = fmaxf(pmax, prob);
    }
    float sgn = (d > 0.f) ? 1.f : ((d < 0.f) ? -1.f : 0.f);
    float inv = 1.0f / pmax;
    float* row = pos + (long)m * PNRP;
    #pragma unroll
    for (int i = 0; i < 16; i++) {
        float gv = fg[i] * inv;
        row[i]      = fe[i];
        row[16 + i] = fc[i];
        row[32 + i] = gv;
        row[48 + i] = sgn * fe[i];
        row[64 + i] = sgn * fc[i];
        row[80 + i] = sgn * gv;
    }
}

// ---------------- kb = k * SCALE + rel_pos_bias ----------------
__global__ void kb_k(const float* __restrict__ k, const float* __restrict__ rpb,
                     float* __restrict__ kb, int total)
{
    for (int i = blockIdx.x * blockDim.x + threadIdx.x; i < total;
         i += gridDim.x * blockDim.x)
        kb[i] = k[i] * PSCALE + rpb[i & 511];
}

// ---------------- fused rel-shift gather + softmax ----------------
__global__ __launch_bounds__(128) void softmax_k(float* __restrict__ att,
                                                 const float* __restrict__ rel)
{
    int i = blockIdx.x;
    long z = blockIdx.y;
    float* row = att + (z * PN1 + i) * (long)PN2;
    const float* relz = rel + z * (long)PN2 * PMQ;
    int t = threadIdx.x, lane = t & 31, wid = t >> 5;

    float v[4];
    float mx = -1e30f;
    #pragma unroll
    for (int u = 0; u < 4; u++) {
        int j = t + u * 128;
        float val = row[j] + relz[(long)j * PMQ + (i + (PN2 - 1) - j)];
        v[u] = val;
        mx = fmaxf(mx, val);
    }
    __shared__ float sh[4];
    mx = warpMax(mx);
    if (lane == 0) sh[wid] = mx;
    __syncthreads();
    float gmx = fmaxf(fmaxf(sh[0], sh[1]), fmaxf(sh[2], sh[3]));
    __syncthreads();

    float s = 0.f;
    #pragma unroll
    for (int u = 0; u < 4; u++) { v[u] = expf(v[u] - gmx); s += v[u]; }
    s = warpSum(s);
    if (lane == 0) sh[wid] = s;
    __syncthreads();
    float gs = sh[0] + sh[1] + sh[2] + sh[3];
    float inv = 1.0f / gs;
    #pragma unroll
    for (int u = 0; u < 4; u++) row[t + u * 128] = v[u] * inv;
}

// ---------------- host orchestration ----------------
static inline dim3 ggrid(int M, int N, int Z) {
    return dim3((unsigned)((N + BN - 1) / BN), (unsigned)((M + BM - 1) / BM), (unsigned)Z);
}

extern "C" void kernel_launch(void* const* d_in, const int* in_sizes, int n_in,
                              void* d_out, int out_size)
{
    const float* x     = (const float*)d_in[0];
    const float* y0    = (const float*)d_in[1];
    const float* W_res = (const float*)d_in[2];
    const float* lnx_g = (const float*)d_in[3];
    const float* lnx_b = (const float*)d_in[4];
    const float* lny_g = (const float*)d_in[5];
    const float* lny_b = (const float*)d_in[6];
    const float* Wq    = (const float*)d_in[7];
    const float* Wk    = (const float*)d_in[8];
    const float* Wv1   = (const float*)d_in[9];
    const float* Wv2   = (const float*)d_in[10];
    const float* Wo1   = (const float*)d_in[11];
    const float* bo1   = (const float*)d_in[12];
    const float* Wo2   = (const float*)d_in[13];
    const float* bo2   = (const float*)d_in[14];
    const float* Wrel  = (const float*)d_in[15];
    const float* rpb   = (const float*)d_in[16];
    const float* fx_g  = (const float*)d_in[17];
    const float* fx_b  = (const float*)d_in[18];
    const float* fx_w1 = (const float*)d_in[19];
    const float* fx_b1 = (const float*)d_in[20];
    const float* fx_w2 = (const float*)d_in[21];
    const float* fx_b2 = (const float*)d_in[22];
    const float* fy_g  = (const float*)d_in[23];
    const float* fy_b  = (const float*)d_in[24];
    const float* fy_w1 = (const float*)d_in[25];
    const float* fy_b1 = (const float*)d_in[26];
    const float* fy_w2 = (const float*)d_in[27];
    const float* fy_b2 = (const float*)d_in[28];

    float* S = nullptr;
    cudaGetSymbolAddress((void**)&S, g_scratch);
    float* gy   = S + OFF_Y;
    float* gx1  = S + OFF_X1;
    float* gy1  = S + OFF_Y1;
    float* gq   = S + OFF_Q;
    float* gk   = S + OFF_K;
    float* gkb  = S + OFF_KB;
    float* gv1  = S + OFF_V1;
    float* gv2  = S + OFF_V2;
    float* gpos = S + OFF_POS;
    float* grq  = S + OFF_RELQ;
    float* grel = S + OFF_REL;
    float* gatt = S + OFF_ATT;
    float* go1  = S + OFF_OUT1;
    float* go2  = S + OFF_OUT2;
    float* gx4  = S + OFF_X4;
    float* gy4  = S + OFF_Y4;
    float* gh   = S + OFF_HID;

    float* outx = (float*)d_out;
    float* outy = outx + (long)PB * PN1 * PD;

    const int HDK = PH * PDK;   // 512
    const int HDV = PH * PDV;   // 768

    // x1 = LN(x), y = y0 @ W_res, y1 = LN(y)
    ln_k<<<PB * PN1, 256>>>(x, lnx_g, lnx_b, gx1);
    gemm_k<false,false><<<ggrid(PB*PN2, PD, 1), 256>>>(y0, W_res, nullptr, nullptr, gy,
        PB*PN2, PD, PDY0, PDY0, PD, PD, 0,0,0,0,0,0, 1, 1.f, 0);
    ln_k<<<PB * PN2, 256>>>(gy, lny_g, lny_b, gy1);

    // q, k, v2, v1 projections
    gemm_k<false,false><<<ggrid(PB*PN1, HDK, 1), 256>>>(gx1, Wq, nullptr, nullptr, gq,
        PB*PN1, HDK, PD, PD, HDK, HDK, 0,0,0,0,0,0, 1, 1.f, 0);
    gemm_k<false,false><<<ggrid(PB*PN2, HDK, 1), 256>>>(gy1, Wk, nullptr, nullptr, gk,
        PB*PN2, HDK, PD, PD, HDK, HDK, 0,0,0,0,0,0, 1, 1.f, 0);
    gemm_k<false,false><<<ggrid(PB*PN2, HDV, 1), 256>>>(gy1, Wv2, nullptr, nullptr, gv2,
        PB*PN2, HDV, PD, PD, HDV, HDV, 0,0,0,0,0,0, 1, 1.f, 0);
    gemm_k<false,false><<<ggrid(PB*PN1, HDV, 1), 256>>>(gx1, Wv1, nullptr, nullptr, gv1,
        PB*PN1, HDV, PD, PD, HDV, HDV, 0,0,0,0,0,0, 1, 1.f, 0);

    // positional features + rel_q = pos @ Wrel (only m < PMQ needed)
    pos_k<<<(PMQ + 127) / 128, 128>>>(gpos);
    gemm_k<false,false><<<ggrid(PMQ, HDK, 1), 256>>>(gpos, Wrel, nullptr, nullptr, grq,
        PMQ, HDK, PNRP, PNRP, HDK, HDK, 0,0,0,0,0,0, 1, 1.f, 0);

    // kb = k * SCALE + rel_pos_bias
    kb_k<<<2048, 256>>>(gk, rpb, gkb, PB*PN2*HDK);

    // content logits = SCALE * q @ k^T   (batched over b,h; NT)
    gemm_k<false,true><<<ggrid(PN1, PN2, PB*PH), 256>>>(gq, gk, nullptr, nullptr, gatt,
        PN1, PN2, PDK, HDK, HDK, PN2,
        (long)PN1*HDK, PDK, (long)PN2*HDK, PDK,
        (long)PH*PN1*PN2, (long)PN1*PN2, PH, PSCALE, 0);

    // rel = kb @ rel_q^T  (batched; rel_q shared across b -> sBb = 0)
    gemm_k<false,true><<<ggrid(PN2, PMQ, PB*PH), 256>>>(gkb, grq, nullptr, nullptr, grel,
        PN2, PMQ, PDK, HDK, HDK, PMQ,
        (long)PN2*HDK, PDK, 0L, PDK,
        (long)PH*PN2*PMQ, (long)PN2*PMQ, PH, 1.f, 0);

    // fused rel-shift gather + softmax (in place over gatt)
    softmax_k<<<dim3(PN1, PB*PH), 128>>>(gatt, grel);

    // out1 = attn @ v2   (batched NN)
    gemm_k<false,false><<<ggrid(PN1, PDV, PB*PH), 256>>>(gatt, gv2, nullptr, nullptr, go1,
        PN1, PDV, PN2, PN2, HDV, HDV,
        (long)PH*PN1*PN2, (long)PN1*PN2, (long)PN2*HDV, PDV,
        (long)PN1*HDV, PDV, PH, 1.f, 0);

    // out2 = attn^T @ v1 (batched TN)
    gemm_k<true,false><<<ggrid(PN2, PDV, PB*PH), 256>>>(gatt, gv1, nullptr, nullptr, go2,
        PN2, PDV, PN1, PN2, HDV, HDV,
        (long)PH*PN1*PN2, (long)PN1*PN2, (long)PN1*HDV, PDV,
        (long)PN2*HDV, PDV, PH, 1.f, 0);

    // x4 = x + out1 @ Wo1 + bo1 ;  y4 = y + out2 @ Wo2 + bo2
    gemm_k<false,false><<<ggrid(PB*PN1, PD, 1), 256>>>(go1, Wo1, bo1, x, gx4,
        PB*PN1, PD, HDV, HDV, PD, PD, 0,0,0,0,0,0, 1, 1.f, 0);
    gemm_k<false,false><<<ggrid(PB*PN2, PD, 1), 256>>>(go2, Wo2, bo2, gy, gy4,
        PB*PN2, PD, HDV, HDV, PD, PD, 0,0,0,0,0,0, 1, 1.f, 0);

    // FFN x: x5 = x4 + relu(LN(x4) @ w1 + b1) @ w2 + b2  -> outx
    ln_k<<<PB * PN1, 256>>>(gx4, fx_g, fx_b, gx1);
    gemm_k<false,false><<<ggrid(PB*PN1, PDFF, 1), 256>>>(gx1, fx_w1, fx_b1, nullptr, gh,
        PB*PN1, PDFF, PD, PD, PDFF, PDFF, 0,0,0,0,0,0, 1, 1.f, 1);
    gemm_k<false,false><<<ggrid(PB*PN1, PD, 1), 256>>>(gh, fx_w2, fx_b2, gx4, outx,
        PB*PN1, PD, PDFF, PDFF, PD, PD, 0,0,0,0,0,0, 1, 1.f, 0);

    // FFN y -> outy
    ln_k<<<PB * PN2, 256>>>(gy4, fy_g, fy_b, gy1);
    gemm_k<false,false><<<ggrid(PB*PN2, PDFF, 1), 256>>>(gy1, fy_w1, fy_b1, nullptr, gh,
        PB*PN2, PDFF, PD, PD, PDFF, PDFF, 0,0,0,0,0,0, 1, 1.f, 1);
    gemm_k<false,false><<<ggrid(PB*PN2, PD, 1), 256>>>(gh, fy_w2, fy_b2, gy4, outy,
        PB*PN2, PD, PDFF, PDFF, PD, PD, 0,0,0,0,0,0, 1, 1.f, 0);

    (void)in_sizes; (void)n_in; (void)out_size;
}